// round 12
// baseline (speedup 1.0000x reference)
#include <cuda_runtime.h>
#include <cuda_bf16.h>
#include <cstdint>

#define N 4096
#define DF 64
#define CLUSTER 4
#define COLS_PER_CTA (N / CLUSTER)   // 1024

// Scratch (allocation-free rule: __device__ globals)
__device__ float g_D[(size_t)N * N];   // 64 MB distance matrix, diagonal = +inf
__device__ float g_sq[N];              // squared norms

__device__ __forceinline__ float finf() { return __int_as_float(0x7f800000); }

// ---------------------------------------------------------------------------
// Kernel 0: squared norms
// ---------------------------------------------------------------------------
__global__ void sq_kernel(const float* __restrict__ x) {
    int i = blockIdx.x * blockDim.x + threadIdx.x;
    if (i >= N) return;
    const float4* xi = (const float4*)(x + (size_t)i * DF);
    float s = 0.f;
#pragma unroll
    for (int k = 0; k < DF / 4; k++) {
        float4 v = xi[k];
        s += v.x * v.x + v.y * v.y + v.z * v.z + v.w * v.w;
    }
    g_sq[i] = s;
}

// ---------------------------------------------------------------------------
// Kernel 1: distance matrix, 64x64 tiles, 256 threads, 4x4 per thread.
// ---------------------------------------------------------------------------
__global__ __launch_bounds__(256) void dist_kernel(const float* __restrict__ x) {
    __shared__ __align__(16) float sA[DF * 68];
    __shared__ __align__(16) float sB[DF * 68];

    const int t    = threadIdx.x;
    const int lrow = t >> 2;      // 0..63
    const int q    = t & 3;       // 0..3
    const int i0   = blockIdx.y * 64;
    const int j0   = blockIdx.x * 64;

    {
        const float4* xa = (const float4*)(x + (size_t)(i0 + lrow) * DF) + q * 4;
        const float4* xb = (const float4*)(x + (size_t)(j0 + lrow) * DF) + q * 4;
#pragma unroll
        for (int u = 0; u < 4; u++) {
            float4 va = xa[u];
            float4 vb = xb[u];
            int k0 = q * 16 + u * 4;
            sA[(k0 + 0) * 68 + lrow] = va.x;
            sA[(k0 + 1) * 68 + lrow] = va.y;
            sA[(k0 + 2) * 68 + lrow] = va.z;
            sA[(k0 + 3) * 68 + lrow] = va.w;
            sB[(k0 + 0) * 68 + lrow] = vb.x;
            sB[(k0 + 1) * 68 + lrow] = vb.y;
            sB[(k0 + 2) * 68 + lrow] = vb.z;
            sB[(k0 + 3) * 68 + lrow] = vb.w;
        }
    }
    __syncthreads();

    const int tx = t & 15;
    const int ty = t >> 4;

    float acc[4][4];
#pragma unroll
    for (int r = 0; r < 4; r++)
#pragma unroll
        for (int c = 0; c < 4; c++) acc[r][c] = 0.f;

#pragma unroll 8
    for (int k = 0; k < DF; k++) {
        float4 a = *(const float4*)&sA[k * 68 + ty * 4];
        float4 b = *(const float4*)&sB[k * 68 + tx * 4];
        float av[4] = {a.x, a.y, a.z, a.w};
        float bv[4] = {b.x, b.y, b.z, b.w};
#pragma unroll
        for (int r = 0; r < 4; r++)
#pragma unroll
            for (int c = 0; c < 4; c++) acc[r][c] = fmaf(av[r], bv[c], acc[r][c]);
    }

    float sqI[4], sqJ[4];
#pragma unroll
    for (int r = 0; r < 4; r++) sqI[r] = g_sq[i0 + ty * 4 + r];
#pragma unroll
    for (int c = 0; c < 4; c++) sqJ[c] = g_sq[j0 + tx * 4 + c];

#pragma unroll
    for (int r = 0; r < 4; r++) {
        int gi = i0 + ty * 4 + r;
        float4 o;
        float ov[4];
#pragma unroll
        for (int c = 0; c < 4; c++) {
            int gj = j0 + tx * 4 + c;
            float d2 = sqI[r] + sqJ[c] - 2.f * acc[r][c];
            float d  = sqrtf(fmaxf(d2, 1e-12f));
            ov[c] = (gi == gj) ? finf() : d;
        }
        o.x = ov[0]; o.y = ov[1]; o.z = ov[2]; o.w = ov[3];
        *(float4*)(g_D + (size_t)gi * N + j0 + tx * 4) = o;
    }
}

// ---------------------------------------------------------------------------
// Kernel 2: Prim scan across a 4-CTA CLUSTER (4 SMs).
//
// CTA `rank` owns columns [rank*1024, rank*1024+1024): 256 threads x 4 elems
// in registers. Per step each CTA loads only its 4KB row slice (vs 16KB on
// one SM), does a tiny merge+tree (~15 instr/warp) and a stage-1 REDUX pair.
// The 8 warp-keys per CTA (32 total) are exchanged ALL-TO-ALL via
// mapa + st.shared::cluster.b64 (fire-and-forget DSMEM stores); every warp
// polls its 32 local slots (lane <-> slot) and runs the exact two-REDUX
// final. Selection semantics are bit-identical to the R5 kernel:
// min on exact fp32 bits, ties -> lowest global index (REDUX on idx);
// in-tree sentinel -1.0f sorts after +inf under unsigned compare.
//
// Slot protocol (proved in R10): key = value<<32 | tag<<31 | idx(12b),
// tag=(step>>1)&1, slots double-buffered by step&1, initialized to tag=1
// before a single cluster.sync(). A slot buffer is only overwritten at
// step s+2, which requires passing the step-(s+1) poll, which requires all
// warps to have consumed step s. No barriers inside the loop.
// ---------------------------------------------------------------------------
__global__ void __cluster_dims__(CLUSTER, 1, 1) __launch_bounds__(256, 1)
prim_kernel(float* __restrict__ out) {
    __shared__ __align__(16) unsigned long long s_slot[2][32];

    unsigned rank;
    asm("mov.u32 %0, %%cluster_ctarank;" : "=r"(rank));

    const int tid  = threadIdx.x;
    const int lane = tid & 31;
    const int wid  = tid >> 5;
    const int base = (int)rank * COLS_PER_CTA + tid * 4;  // global col of e=0

    float m[4];
#pragma unroll
    for (int e = 0; e < 4; e++) m[e] = finf();
    if (rank == 0 && tid == 0) m[0] = -1.0f;   // vertex 0 starts in the tree

    // init slots (tag=1) in every CTA, then cluster-wide sync so no remote
    // store can land before its target slot is initialized
    if (tid < 64) s_slot[tid >> 5][tid & 31] = 0x80000000ull;
    asm volatile("barrier.cluster.arrive.aligned;" ::: "memory");
    asm volatile("barrier.cluster.wait.aligned;" ::: "memory");

    // local SMEM base addresses (32-bit shared window)
    unsigned slot_base;
    {
        void* pp = (void*)&s_slot[0][0];
        asm("{ .reg .u64 t; cvta.to.shared.u64 t, %1; cvt.u32.u64 %0, t; }"
            : "=r"(slot_base) : "l"(pp));
    }

    int      j          = 0;
    unsigned prev_death = 0;
    const int myslot    = (int)rank * 8 + wid;

    for (int step = 0; step < N - 1; step++) {
        const int      par  = step & 1;
        const unsigned want = (unsigned)((step >> 1) & 1);

        // ---- 1. this CTA's 4KB slice of row j (1 LDG.128 per thread)
        const float4* rp =
            (const float4*)(g_D + ((size_t)j << 12) + rank * COLS_PER_CTA) + tid;
        float4 d = __ldcg(rp);

        // ---- 2. deferred output for the previous step (off-path)
        if (step > 0 && rank == 0 && tid == 0)
            *(float2*)(out + 2 * (step - 1)) =
                make_float2(0.0f, __uint_as_float(prev_death));

        // ---- 3. merge + implicit mask (sentinel bits sort after +inf)
        float dv[4] = {d.x, d.y, d.z, d.w};
        unsigned v[4];
#pragma unroll
        for (int e = 0; e < 4; e++) {
            m[e] = fminf(m[e], dv[e]);
            v[e] = __float_as_uint(m[e]);
        }

        // ---- 4. 3-node local argmin tree (strict < keeps earlier index)
        unsigned b0v = (v[1] < v[0]) ? v[1] : v[0];
        int      b0e = (v[1] < v[0]) ? 1 : 0;
        unsigned b1v = (v[3] < v[2]) ? v[3] : v[2];
        int      b1e = (v[3] < v[2]) ? 3 : 2;
        bool     pp0 = b1v < b0v;
        unsigned myv = pp0 ? b1v : b0v;
        int      e0  = pp0 ? b1e : b0e;
        unsigned myi = (unsigned)(base + e0);

        // ---- 5. stage 1: warp argmin via two REDUX ops (exact)
        unsigned wmin = __reduce_min_sync(0xffffffffu, myv);
        unsigned cand = (myv == wmin) ? myi : 0xffffffffu;
        unsigned widx = __reduce_min_sync(0xffffffffu, cand);

        // ---- 6. publish key to ALL CTAs (fire-and-forget DSMEM stores)
        if (lane == 0) {
            unsigned long long key = ((unsigned long long)wmin << 32)
                                   | ((unsigned long long)want << 31) | widx;
            unsigned laddr = slot_base + (unsigned)(par * 32 + myslot) * 8u;
#pragma unroll
            for (unsigned r = 0; r < CLUSTER; r++) {
                unsigned raddr;
                asm("mapa.shared::cluster.u32 %0, %1, %2;"
                    : "=r"(raddr) : "r"(laddr), "r"(r));
                asm volatile("st.shared::cluster.u64 [%0], %1;"
                             :: "r"(raddr), "l"(key) : "memory");
            }
        }

        // ---- 7. poll own 32 slots until every key carries this step's tag
        const volatile unsigned long long* sl = &s_slot[par][0];
        unsigned long long k8;
        for (;;) {
            k8 = sl[lane];
            bool rdy = (((unsigned)(k8 >> 31)) & 1u) == want;
            if (__ballot_sync(0xffffffffu, rdy) == 0xffffffffu) break;
        }

        // ---- 8. final: exact two-REDUX over the 32 keys (all warps, all CTAs)
        unsigned kv   = (unsigned)(k8 >> 32);
        unsigned gmin = __reduce_min_sync(0xffffffffu, kv);
        unsigned c2   = (kv == gmin) ? (unsigned)k8 : 0xffffffffu;
        unsigned gidx = __reduce_min_sync(0xffffffffu, c2);
        unsigned gi   = gidx & 0xFFFu;   // strip tag; idx is 12 bits

        // ---- 9. bookkeeping
        j          = (int)gi;
        prev_death = gmin;

        if ((gi >> 10) == rank) {                 // owning CTA
            int tof = (int)((gi >> 2) & 0xFFu);   // owning thread
            if (tof == tid) m[gi & 3u] = -1.0f;   // sentinel joins tree
        }
    }

    // final deferred output
    if (rank == 0 && tid == 0)
        *(float2*)(out + 2 * (N - 2)) =
            make_float2(0.0f, __uint_as_float(prev_death));

    // no CTA may exit while peers could still address its SMEM
    asm volatile("barrier.cluster.arrive.aligned;" ::: "memory");
    asm volatile("barrier.cluster.wait.aligned;" ::: "memory");
}

// ---------------------------------------------------------------------------
extern "C" void kernel_launch(void* const* d_in, const int* in_sizes, int n_in,
                              void* d_out, int out_size) {
    const float* x   = (const float*)d_in[0];
    float*       out = (float*)d_out;

    sq_kernel<<<(N + 255) / 256, 256>>>(x);
    dim3 grid(N / 64, N / 64);
    dist_kernel<<<grid, 256>>>(x);
    prim_kernel<<<CLUSTER, 256>>>(out);
}

// round 13
// speedup vs baseline: 1.0490x; 1.0490x over previous
#include <cuda_runtime.h>
#include <cuda_bf16.h>
#include <cstdint>

#define N 4096
#define DF 64
#define CLUSTER 4
#define COLS_PER_CTA (N / CLUSTER)   // 1024

// Scratch (allocation-free rule: __device__ globals)
__device__ float g_D[(size_t)N * N];   // 64 MB distance matrix, diagonal = +inf
__device__ float g_sq[N];              // squared norms

__device__ __forceinline__ float finf() { return __int_as_float(0x7f800000); }

// ---------------------------------------------------------------------------
// Kernel 0: squared norms
// ---------------------------------------------------------------------------
__global__ void sq_kernel(const float* __restrict__ x) {
    int i = blockIdx.x * blockDim.x + threadIdx.x;
    if (i >= N) return;
    const float4* xi = (const float4*)(x + (size_t)i * DF);
    float s = 0.f;
#pragma unroll
    for (int k = 0; k < DF / 4; k++) {
        float4 v = xi[k];
        s += v.x * v.x + v.y * v.y + v.z * v.z + v.w * v.w;
    }
    g_sq[i] = s;
}

// ---------------------------------------------------------------------------
// Kernel 1: distance matrix, 64x64 tiles, 256 threads, 4x4 per thread.
// ---------------------------------------------------------------------------
__global__ __launch_bounds__(256) void dist_kernel(const float* __restrict__ x) {
    __shared__ __align__(16) float sA[DF * 68];
    __shared__ __align__(16) float sB[DF * 68];

    const int t    = threadIdx.x;
    const int lrow = t >> 2;      // 0..63
    const int q    = t & 3;       // 0..3
    const int i0   = blockIdx.y * 64;
    const int j0   = blockIdx.x * 64;

    {
        const float4* xa = (const float4*)(x + (size_t)(i0 + lrow) * DF) + q * 4;
        const float4* xb = (const float4*)(x + (size_t)(j0 + lrow) * DF) + q * 4;
#pragma unroll
        for (int u = 0; u < 4; u++) {
            float4 va = xa[u];
            float4 vb = xb[u];
            int k0 = q * 16 + u * 4;
            sA[(k0 + 0) * 68 + lrow] = va.x;
            sA[(k0 + 1) * 68 + lrow] = va.y;
            sA[(k0 + 2) * 68 + lrow] = va.z;
            sA[(k0 + 3) * 68 + lrow] = va.w;
            sB[(k0 + 0) * 68 + lrow] = vb.x;
            sB[(k0 + 1) * 68 + lrow] = vb.y;
            sB[(k0 + 2) * 68 + lrow] = vb.z;
            sB[(k0 + 3) * 68 + lrow] = vb.w;
        }
    }
    __syncthreads();

    const int tx = t & 15;
    const int ty = t >> 4;

    float acc[4][4];
#pragma unroll
    for (int r = 0; r < 4; r++)
#pragma unroll
        for (int c = 0; c < 4; c++) acc[r][c] = 0.f;

#pragma unroll 8
    for (int k = 0; k < DF; k++) {
        float4 a = *(const float4*)&sA[k * 68 + ty * 4];
        float4 b = *(const float4*)&sB[k * 68 + tx * 4];
        float av[4] = {a.x, a.y, a.z, a.w};
        float bv[4] = {b.x, b.y, b.z, b.w};
#pragma unroll
        for (int r = 0; r < 4; r++)
#pragma unroll
            for (int c = 0; c < 4; c++) acc[r][c] = fmaf(av[r], bv[c], acc[r][c]);
    }

    float sqI[4], sqJ[4];
#pragma unroll
    for (int r = 0; r < 4; r++) sqI[r] = g_sq[i0 + ty * 4 + r];
#pragma unroll
    for (int c = 0; c < 4; c++) sqJ[c] = g_sq[j0 + tx * 4 + c];

#pragma unroll
    for (int r = 0; r < 4; r++) {
        int gi = i0 + ty * 4 + r;
        float4 o;
        float ov[4];
#pragma unroll
        for (int c = 0; c < 4; c++) {
            int gj = j0 + tx * 4 + c;
            float d2 = sqI[r] + sqJ[c] - 2.f * acc[r][c];
            float d  = sqrtf(fmaxf(d2, 1e-12f));
            ov[c] = (gi == gj) ? finf() : d;
        }
        o.x = ov[0]; o.y = ov[1]; o.z = ov[2]; o.w = ov[3];
        *(float4*)(g_D + (size_t)gi * N + j0 + tx * 4) = o;
    }
}

// ---------------------------------------------------------------------------
// Kernel 2: Prim scan across a 4-CTA CLUSTER (4 SMs) — v2.
//
// Identical selection semantics to the proven R12 kernel (bit-exact
// jnp.argmin: exact fp32 bits, ties -> lowest global index; sentinel -1.0f
// sorts after +inf under unsigned compare; tag-in-key slot protocol with
// double buffering and a single init-time cluster.sync).
//
// v2 change: PARALLEL PUBLISH. All lanes hold the warp key after the two
// stage-1 REDUX ops, so lanes 0..3 each store the key to one cluster rank
// via a single predicated st.shared::cluster.b64 (per-lane mapa address) —
// one instruction issues all 4 remote stores, instead of lane0 serializing
// 4 remote stores (remote STS bills the producer; the serial chain was
// ~150-250 cyc of pure critical-path overhead in R12).
// ---------------------------------------------------------------------------
__global__ void __cluster_dims__(CLUSTER, 1, 1) __launch_bounds__(256, 1)
prim_kernel(float* __restrict__ out) {
    __shared__ __align__(16) unsigned long long s_slot[2][32];

    unsigned rank;
    asm("mov.u32 %0, %%cluster_ctarank;" : "=r"(rank));

    const int tid  = threadIdx.x;
    const int lane = tid & 31;
    const int wid  = tid >> 5;
    const int base = (int)rank * COLS_PER_CTA + tid * 4;  // global col of e=0

    float m[4];
#pragma unroll
    for (int e = 0; e < 4; e++) m[e] = finf();
    if (rank == 0 && tid == 0) m[0] = -1.0f;   // vertex 0 starts in the tree

    // init slots (tag=1) in every CTA, then cluster-wide sync so no remote
    // store can land before its target slot is initialized
    if (tid < 64) s_slot[tid >> 5][tid & 31] = 0x80000000ull;
    asm volatile("barrier.cluster.arrive.aligned;" ::: "memory");
    asm volatile("barrier.cluster.wait.aligned;" ::: "memory");

    // local SMEM base address (32-bit shared window)
    unsigned slot_base;
    {
        void* pp = (void*)&s_slot[0][0];
        asm("{ .reg .u64 t; cvta.to.shared.u64 t, %1; cvt.u32.u64 %0, t; }"
            : "=r"(slot_base) : "l"(pp));
    }

    int      j          = 0;
    unsigned prev_death = 0;
    const int myslot    = (int)rank * 8 + wid;

    for (int step = 0; step < N - 1; step++) {
        const int      par  = step & 1;
        const unsigned want = (unsigned)((step >> 1) & 1);

        // ---- 1. this CTA's 4KB slice of row j (1 LDG.128 per thread)
        const float4* rp =
            (const float4*)(g_D + ((size_t)j << 12) + rank * COLS_PER_CTA) + tid;
        float4 d = __ldcg(rp);

        // ---- 2. deferred output for the previous step (under load shadow)
        if (step > 0 && rank == 0 && tid == 0)
            *(float2*)(out + 2 * (step - 1)) =
                make_float2(0.0f, __uint_as_float(prev_death));

        // ---- 3. merge + implicit mask (sentinel bits sort after +inf)
        float dv[4] = {d.x, d.y, d.z, d.w};
        unsigned v[4];
#pragma unroll
        for (int e = 0; e < 4; e++) {
            m[e] = fminf(m[e], dv[e]);
            v[e] = __float_as_uint(m[e]);
        }

        // ---- 4. 3-node local argmin tree (strict < keeps earlier index)
        unsigned b0v = (v[1] < v[0]) ? v[1] : v[0];
        int      b0e = (v[1] < v[0]) ? 1 : 0;
        unsigned b1v = (v[3] < v[2]) ? v[3] : v[2];
        int      b1e = (v[3] < v[2]) ? 3 : 2;
        bool     pp0 = b1v < b0v;
        unsigned myv = pp0 ? b1v : b0v;
        int      e0  = pp0 ? b1e : b0e;
        unsigned myi = (unsigned)(base + e0);

        // ---- 5. stage 1: warp argmin via two REDUX ops (exact)
        unsigned wmin = __reduce_min_sync(0xffffffffu, myv);
        unsigned cand = (myv == wmin) ? myi : 0xffffffffu;
        unsigned widx = __reduce_min_sync(0xffffffffu, cand);

        // ---- 6. PARALLEL publish: lanes 0..3 each store to one rank.
        //         One predicated STS.64 issues all 4 remote stores at once.
        {
            unsigned long long key = ((unsigned long long)wmin << 32)
                                   | ((unsigned long long)want << 31) | widx;
            if (lane < CLUSTER) {
                unsigned laddr = slot_base + (unsigned)(par * 32 + myslot) * 8u;
                unsigned raddr;
                asm("mapa.shared::cluster.u32 %0, %1, %2;"
                    : "=r"(raddr) : "r"(laddr), "r"((unsigned)lane));
                asm volatile("st.shared::cluster.u64 [%0], %1;"
                             :: "r"(raddr), "l"(key) : "memory");
            }
        }

        // ---- 7. poll own 32 slots until every key carries this step's tag
        const volatile unsigned long long* sl = &s_slot[par][0];
        unsigned long long k8;
        for (;;) {
            k8 = sl[lane];
            bool rdy = (((unsigned)(k8 >> 31)) & 1u) == want;
            if (__ballot_sync(0xffffffffu, rdy) == 0xffffffffu) break;
        }

        // ---- 8. final: exact two-REDUX over the 32 keys (all warps, all CTAs)
        unsigned kv   = (unsigned)(k8 >> 32);
        unsigned gmin = __reduce_min_sync(0xffffffffu, kv);
        unsigned c2   = (kv == gmin) ? (unsigned)k8 : 0xffffffffu;
        unsigned gidx = __reduce_min_sync(0xffffffffu, c2);
        unsigned gi   = gidx & 0xFFFu;   // strip tag; idx is 12 bits

        // ---- 9. bookkeeping
        j          = (int)gi;
        prev_death = gmin;
        if ((gi & ~3u) == (unsigned)base)   // owner thread
            m[gi & 3u] = -1.0f;             // sentinel joins tree
    }

    // final deferred output
    if (rank == 0 && tid == 0)
        *(float2*)(out + 2 * (N - 2)) =
            make_float2(0.0f, __uint_as_float(prev_death));

    // no CTA may exit while peers could still address its SMEM
    asm volatile("barrier.cluster.arrive.aligned;" ::: "memory");
    asm volatile("barrier.cluster.wait.aligned;" ::: "memory");
}

// ---------------------------------------------------------------------------
extern "C" void kernel_launch(void* const* d_in, const int* in_sizes, int n_in,
                              void* d_out, int out_size) {
    const float* x   = (const float*)d_in[0];
    float*       out = (float*)d_out;

    sq_kernel<<<(N + 255) / 256, 256>>>(x);
    dim3 grid(N / 64, N / 64);
    dist_kernel<<<grid, 256>>>(x);
    prim_kernel<<<CLUSTER, 256>>>(out);
}

// round 14
// speedup vs baseline: 1.1065x; 1.0548x over previous
#include <cuda_runtime.h>
#include <cuda_bf16.h>
#include <cstdint>

#define N 4096
#define DF 64

// Scratch (allocation-free rule: __device__ globals)
__device__ float g_D[(size_t)N * N];   // 64 MB distance matrix, diagonal = +inf
__device__ float g_sq[N];              // squared norms

__device__ __forceinline__ float finf() { return __int_as_float(0x7f800000); }

// ---------------------------------------------------------------------------
// Kernel 0: squared norms
// ---------------------------------------------------------------------------
__global__ void sq_kernel(const float* __restrict__ x) {
    int i = blockIdx.x * blockDim.x + threadIdx.x;
    if (i >= N) return;
    const float4* xi = (const float4*)(x + (size_t)i * DF);
    float s = 0.f;
#pragma unroll
    for (int k = 0; k < DF / 4; k++) {
        float4 v = xi[k];
        s += v.x * v.x + v.y * v.y + v.z * v.z + v.w * v.w;
    }
    g_sq[i] = s;
}

// ---------------------------------------------------------------------------
// Kernel 1: distance matrix, 64x64 tiles, 256 threads, 4x4 per thread.
// ---------------------------------------------------------------------------
__global__ __launch_bounds__(256) void dist_kernel(const float* __restrict__ x) {
    __shared__ __align__(16) float sA[DF * 68];
    __shared__ __align__(16) float sB[DF * 68];

    const int t    = threadIdx.x;
    const int lrow = t >> 2;      // 0..63
    const int q    = t & 3;       // 0..3
    const int i0   = blockIdx.y * 64;
    const int j0   = blockIdx.x * 64;

    {
        const float4* xa = (const float4*)(x + (size_t)(i0 + lrow) * DF) + q * 4;
        const float4* xb = (const float4*)(x + (size_t)(j0 + lrow) * DF) + q * 4;
#pragma unroll
        for (int u = 0; u < 4; u++) {
            float4 va = xa[u];
            float4 vb = xb[u];
            int k0 = q * 16 + u * 4;
            sA[(k0 + 0) * 68 + lrow] = va.x;
            sA[(k0 + 1) * 68 + lrow] = va.y;
            sA[(k0 + 2) * 68 + lrow] = va.z;
            sA[(k0 + 3) * 68 + lrow] = va.w;
            sB[(k0 + 0) * 68 + lrow] = vb.x;
            sB[(k0 + 1) * 68 + lrow] = vb.y;
            sB[(k0 + 2) * 68 + lrow] = vb.z;
            sB[(k0 + 3) * 68 + lrow] = vb.w;
        }
    }
    __syncthreads();

    const int tx = t & 15;
    const int ty = t >> 4;

    float acc[4][4];
#pragma unroll
    for (int r = 0; r < 4; r++)
#pragma unroll
        for (int c = 0; c < 4; c++) acc[r][c] = 0.f;

#pragma unroll 8
    for (int k = 0; k < DF; k++) {
        float4 a = *(const float4*)&sA[k * 68 + ty * 4];
        float4 b = *(const float4*)&sB[k * 68 + tx * 4];
        float av[4] = {a.x, a.y, a.z, a.w};
        float bv[4] = {b.x, b.y, b.z, b.w};
#pragma unroll
        for (int r = 0; r < 4; r++)
#pragma unroll
            for (int c = 0; c < 4; c++) acc[r][c] = fmaf(av[r], bv[c], acc[r][c]);
    }

    float sqI[4], sqJ[4];
#pragma unroll
    for (int r = 0; r < 4; r++) sqI[r] = g_sq[i0 + ty * 4 + r];
#pragma unroll
    for (int c = 0; c < 4; c++) sqJ[c] = g_sq[j0 + tx * 4 + c];

#pragma unroll
    for (int r = 0; r < 4; r++) {
        int gi = i0 + ty * 4 + r;
        float4 o;
        float ov[4];
#pragma unroll
        for (int c = 0; c < 4; c++) {
            int gj = j0 + tx * 4 + c;
            float d2 = sqI[r] + sqJ[c] - 2.f * acc[r][c];
            float d  = sqrtf(fmaxf(d2, 1e-12f));
            ov[c] = (gi == gj) ? finf() : d;
        }
        o.x = ov[0]; o.y = ov[1]; o.z = ov[2]; o.w = ov[3];
        *(float4*)(g_D + (size_t)gi * N + j0 + tx * 4) = o;
    }
}

// ---------------------------------------------------------------------------
// Kernel 2: Prim scan — R5 proven core (256 threads, 8 warps, 16 elems/thread
// in registers; sentinel -1.0f sorts after +inf under unsigned compare; two
// REDUX per stage => bit-exact jnp.argmin semantics), with three exact
// instruction-removing shaves:
//  (a) gidx[16]: loop-invariant global indices carried through the tree SELs
//      (deletes the per-step index assembly; 1 resident CTA => regs are free)
//  (b) deferred output STG: death = REDUX high word, written one step later
//      under the next row-load's stall (tail of the reduce gets shorter)
//  (c) per-thread 64-bit row base pointer; per-step address = base + (j<<14)
// ---------------------------------------------------------------------------
__global__ __launch_bounds__(256, 1) void prim_kernel(float* __restrict__ out) {
    __shared__ unsigned long long s_warp[2][8];

    const int tid  = threadIdx.x;
    const int lane = tid & 31;
    const int wid  = tid >> 5;
    const int base = wid * 512 + lane * 4;   // global idx of e=0

    // loop-invariant global index constants (idx = base + (e>>2)*128 + (e&3))
    unsigned gidx[16];
#pragma unroll
    for (int e = 0; e < 16; e++)
        gidx[e] = (unsigned)(base + ((e >> 2) << 7) + (e & 3));

    // per-thread byte base of this thread's slice within a row
    const char* rbase = (const char*)g_D + (size_t)(wid * 128 + lane) * 16;

    float m[16];
#pragma unroll
    for (int e = 0; e < 16; e++) m[e] = finf();
    if (tid == 0) m[0] = -1.0f;   // vertex 0 starts in the tree

    int      j          = 0;
    unsigned prev_death = 0;

    for (int step = 0; step < N - 1; step++) {
        const int par = step & 1;

        // ---- 1. row loads first (MLP=4); everything below overlaps them
        const float4* rp = (const float4*)(rbase + ((size_t)j << 14));
        float4 q0 = __ldcg(rp);
        float4 q1 = __ldcg(rp + 32);
        float4 q2 = __ldcg(rp + 64);
        float4 q3 = __ldcg(rp + 96);

        // ---- 2. deferred output for the previous step (under load stall)
        if (step > 0 && tid == 0)
            *(float2*)(out + 2 * (step - 1)) =
                make_float2(0.0f, __uint_as_float(prev_death));

        float dv[16] = {q0.x, q0.y, q0.z, q0.w, q1.x, q1.y, q1.z, q1.w,
                        q2.x, q2.y, q2.z, q2.w, q3.x, q3.y, q3.z, q3.w};

        // ---- 3. merge + implicit mask (sentinel bits sort after +inf)
        unsigned v[16];
#pragma unroll
        for (int e = 0; e < 16; e++) {
            m[e] = fminf(m[e], dv[e]);
            v[e] = __float_as_uint(m[e]);
        }

        // ---- 4. local argmin tree carrying GLOBAL indices
        //         (strict < keeps the earlier/lower index)
        unsigned bv[8], bi[8];
#pragma unroll
        for (int k = 0; k < 8; k++) {
            bool p = v[2 * k + 1] < v[2 * k];
            bv[k] = p ? v[2 * k + 1] : v[2 * k];
            bi[k] = p ? gidx[2 * k + 1] : gidx[2 * k];
        }
#pragma unroll
        for (int k = 0; k < 4; k++) {
            bool p = bv[2 * k + 1] < bv[2 * k];
            bv[k] = p ? bv[2 * k + 1] : bv[2 * k];
            bi[k] = p ? bi[2 * k + 1] : bi[2 * k];
        }
#pragma unroll
        for (int k = 0; k < 2; k++) {
            bool p = bv[2 * k + 1] < bv[2 * k];
            bv[k] = p ? bv[2 * k + 1] : bv[2 * k];
            bi[k] = p ? bi[2 * k + 1] : bi[2 * k];
        }
        bool p0 = bv[1] < bv[0];
        unsigned myv = p0 ? bv[1] : bv[0];
        unsigned myi = p0 ? bi[1] : bi[0];

        // ---- 5. stage 1: warp argmin via two REDUX ops (exact)
        unsigned wmin = __reduce_min_sync(0xffffffffu, myv);
        unsigned cand = (myv == wmin) ? myi : 0xffffffffu;
        unsigned widx = __reduce_min_sync(0xffffffffu, cand);
        if (lane == 0)
            s_warp[par][wid] = ((unsigned long long)wmin << 32) | widx;
        __syncthreads();

        // ---- 6. stage 2: every warp redundantly reduces the 8 per-warp keys
        unsigned long long k8 =
            (lane < 8) ? s_warp[par][lane] : 0xffffffffffffffffull;
        unsigned kv   = (unsigned)(k8 >> 32);
        unsigned gmin = __reduce_min_sync(0xffffffffu, kv);
        unsigned c2   = (kv == gmin) ? (unsigned)k8 : 0xffffffffu;
        unsigned gi   = __reduce_min_sync(0xffffffffu, c2);

        // ---- 7. bookkeeping (next LDG needs only j; STG deferred to top)
        j          = (int)gi;
        prev_death = gmin;

        int own = (int)(((gi >> 9) << 5) | ((gi >> 2) & 31));
        if (own == tid) {
            int e = (int)(((gi >> 5) & 0xCu) | (gi & 3u));
            m[e] = -1.0f;   // sentinel (survives fminf, sorts last)
        }
    }

    // final deferred output
    if (tid == 0)
        *(float2*)(out + 2 * (N - 2)) =
            make_float2(0.0f, __uint_as_float(prev_death));
}

// ---------------------------------------------------------------------------
extern "C" void kernel_launch(void* const* d_in, const int* in_sizes, int n_in,
                              void* d_out, int out_size) {
    const float* x   = (const float*)d_in[0];
    float*       out = (float*)d_out;

    sq_kernel<<<(N + 255) / 256, 256>>>(x);
    dim3 grid(N / 64, N / 64);
    dist_kernel<<<grid, 256>>>(x);
    prim_kernel<<<1, 256>>>(out);
}